// round 7
// baseline (speedup 1.0000x reference)
#include <cuda_runtime.h>

#define NPOINTS     500000
#define NWAVE       128
#define NOFFSETS    50

#define TPB         128
#define NBLK        1480            // 10 blocks/SM on 148 SMs
#define TILE        128
#define QUOT        337             // NPOINTS / NBLK
#define REMR        1240            // NPOINTS - QUOT*NBLK

#define RB          128             // reduce grid
#define TWO_PI      6.283185307179586f

// Accum-coalesced layout [block][wave].
__device__ float g_partialC[NBLK * NWAVE];
__device__ float g_partialS[NBLK * NWAVE];
// Intermediate [rblock][wave].
__device__ float g2C[RB * NWAVE];
__device__ float g2S[RB * NWAVE];
__device__ unsigned int g_cnt;      // zero-init; finisher resets each run

__global__ __launch_bounds__(TPB, 10)
void accum_kernel(const float2* __restrict__ xy,
                  const float*  __restrict__ tid,
                  const float*  __restrict__ center,
                  const float*  __restrict__ wavelength)
{
    __shared__ float sdist[TILE];

    const int w  = threadIdx.x;
    const float kw = TWO_PI / wavelength[w];
    const float cx = center[0];
    const float cy = center[1];

    // Balanced contiguous range: blocks differ by at most 1 point of work.
    const int b    = blockIdx.x;
    const int base = b * QUOT + min(b, REMR);
    const int cnt  = QUOT + (b < REMR ? 1 : 0);

    float accC = 0.0f;
    float accS = 0.0f;

    for (int t0 = 0; t0 < cnt; t0 += TILE) {
        const int n = min(TILE, cnt - t0);

        if (threadIdx.x < n) {
            const float2 v = xy[base + t0 + threadIdx.x];
            const float dx = v.x - cx;
            const float dy = v.y - cy;
            sdist[threadIdx.x] = sqrtf(fmaf(dx, dx, dy * dy));
        }
        __syncthreads();

        const float* __restrict__ trow = tid + (size_t)(base + t0) * NWAVE + w;

        #pragma unroll 8
        for (int i = 0; i < n; i++) {
            const float t = __ldcs(trow + (size_t)i * NWAVE);  // coalesced row read
            float s, c;
            __sincosf(sdist[i] * kw, &s, &c);                  // 2x MUFU
            accC = fmaf(c, t, accC);
            accS = fmaf(s, t, accS);
        }
        __syncthreads();
    }

    g_partialC[b * NWAVE + w] = accC;    // coalesced row store
    g_partialS[b * NWAVE + w] = accS;
}

// Tail, one launch. Thread mapping (w = t&127, g = t>>7): a warp's lanes
// span 32 consecutive wavelengths of ONE row -> 128B coalesced loads
// against the [block][wave] layout. 256 concurrent row-streams.
__global__ __launch_bounds__(256)
void reduce_kernel(float* __restrict__ out)
{
    __shared__ float smC[2][NWAVE];
    __shared__ float smS[2][NWAVE];
    __shared__ float smM[NWAVE];
    __shared__ unsigned int is_last;

    const int w = threadIdx.x & (NWAVE - 1);
    const int g = threadIdx.x >> 7;

    // Phase 1: strided row sweep, fixed order -> deterministic.
    float c = 0.0f, s = 0.0f;
    #pragma unroll 3
    for (int b = blockIdx.x * 2 + g; b < NBLK; b += RB * 2) {
        c += g_partialC[b * NWAVE + w];
        s += g_partialS[b * NWAVE + w];
    }
    smC[g][w] = c;
    smS[g][w] = s;
    __syncthreads();

    if (g == 0) {
        g2C[blockIdx.x * NWAVE + w] = smC[0][w] + smC[1][w];   // coalesced
        g2S[blockIdx.x * NWAVE + w] = smS[0][w] + smS[1][w];
        __threadfence();
    }
    __syncthreads();
    if (threadIdx.x == 0)
        is_last = (atomicAdd(&g_cnt, 1u) == RB - 1) ? 1u : 0u;
    __syncthreads();
    if (!is_last) return;

    // Finisher: reduce the 128-row intermediate, same coalesced mapping.
    float fc = 0.0f, fs = 0.0f;
    #pragma unroll 8
    for (int r = g; r < RB; r += 2) {            // 64 iters per thread
        fc += g2C[r * NWAVE + w];
        fs += g2S[r * NWAVE + w];
    }
    smC[g][w] = fc;
    smS[g][w] = fs;
    __syncthreads();

    if (g == 0) {
        const float C = (smC[0][w] + smC[1][w]) * (1.0f / (float)NPOINTS);
        const float S = (smS[0][w] + smS[1][w]) * (1.0f / (float)NPOINTS);
        float m = -3.402823466e38f;
        #pragma unroll
        for (int i = 0; i < NOFFSETS; i++) {
            const float o = (float)i * (TWO_PI / (float)(NOFFSETS - 1));
            const float v = C * cosf(o) - S * sinf(o);
            m = fmaxf(m, v);
        }
        smM[w] = m;
    }
    __syncthreads();

    #pragma unroll
    for (int stride = NWAVE / 2; stride > 0; stride >>= 1) {
        if (threadIdx.x < stride) smM[threadIdx.x] += smM[threadIdx.x + stride];
        __syncthreads();
    }
    if (threadIdx.x == 0) {
        out[0] = -smM[0];
        g_cnt = 0;                 // reset for next graph replay
    }
}

extern "C" void kernel_launch(void* const* d_in, const int* in_sizes, int n_in,
                              void* d_out, int out_size)
{
    const float2* xy         = (const float2*)d_in[0];  // [500000, 2]
    const float*  tid        = (const float*) d_in[1];  // [500000, 128]
    const float*  center     = (const float*) d_in[2];  // [2]
    const float*  wavelength = (const float*) d_in[3];  // [128]
    float* out = (float*)d_out;

    accum_kernel<<<NBLK, TPB>>>(xy, tid, center, wavelength);
    reduce_kernel<<<RB, 256>>>(out);
}

// round 9
// speedup vs baseline: 1.5681x; 1.5681x over previous
#include <cuda_runtime.h>

#define NPOINTS     500000
#define NWAVE       128
#define NOFFSETS    50

#define TPB         128
#define NBLK        1480            // 10 blocks/SM on 148 SMs
#define TILE        128
#define QUOT        337             // NPOINTS / NBLK
#define REMR        1240            // NPOINTS - QUOT*NBLK

#define RB          128             // stage-2 grid
#define TWO_PI      6.283185307179586f

// Accum-native layout [block][wave].
__device__ float g_partialC[NBLK * NWAVE];
__device__ float g_partialS[NBLK * NWAVE];
// Stage-2 output [RB][wave].
__device__ float g2C[RB * NWAVE];
__device__ float g2S[RB * NWAVE];

__global__ __launch_bounds__(TPB, 10)
void accum_kernel(const float2* __restrict__ xy,
                  const float*  __restrict__ tid,
                  const float*  __restrict__ center,
                  const float*  __restrict__ wavelength)
{
    __shared__ float sdist[TILE];

    const int w  = threadIdx.x;
    const float kw = TWO_PI / wavelength[w];
    const float cx = center[0];
    const float cy = center[1];

    // Balanced contiguous range: blocks differ by at most 1 point of work.
    const int b    = blockIdx.x;
    const int base = b * QUOT + min(b, REMR);
    const int cnt  = QUOT + (b < REMR ? 1 : 0);

    float accC = 0.0f;
    float accS = 0.0f;

    for (int t0 = 0; t0 < cnt; t0 += TILE) {
        const int n = min(TILE, cnt - t0);

        if (threadIdx.x < n) {
            const float2 v = xy[base + t0 + threadIdx.x];
            const float dx = v.x - cx;
            const float dy = v.y - cy;
            sdist[threadIdx.x] = sqrtf(fmaf(dx, dx, dy * dy));
        }
        __syncthreads();

        const float* __restrict__ trow = tid + (size_t)(base + t0) * NWAVE + w;

        #pragma unroll 8
        for (int i = 0; i < n; i++) {
            const float t = __ldcs(trow + (size_t)i * NWAVE);  // coalesced row read
            float s, c;
            __sincosf(sdist[i] * kw, &s, &c);                  // 2x MUFU
            accC = fmaf(c, t, accC);
            accS = fmaf(s, t, accS);
        }
        __syncthreads();
    }

    g_partialC[b * NWAVE + w] = accC;    // coalesced row store
    g_partialS[b * NWAVE + w] = accS;
}

// Stage 2: plain kernel, no atomics. Mapping (w = t&127, g = t>>7): a warp's
// lanes span 32 consecutive wavelengths of one row -> fully coalesced
// against [block][wave]. 256 concurrent row streams across 128 blocks.
__global__ __launch_bounds__(256)
void reduce1_kernel()
{
    __shared__ float smC[2][NWAVE];
    __shared__ float smS[2][NWAVE];

    const int w = threadIdx.x & (NWAVE - 1);
    const int g = threadIdx.x >> 7;

    float c = 0.0f, s = 0.0f;
    #pragma unroll 6
    for (int b = blockIdx.x * 2 + g; b < NBLK; b += RB * 2) {  // fixed order
        c += g_partialC[b * NWAVE + w];
        s += g_partialS[b * NWAVE + w];
    }
    smC[g][w] = c;
    smS[g][w] = s;
    __syncthreads();

    if (g == 0) {
        g2C[blockIdx.x * NWAVE + w] = smC[0][w] + smC[1][w];   // coalesced
        g2S[blockIdx.x * NWAVE + w] = smS[0][w] + smS[1][w];
    }
}

// Stage 3: single block, 1024 threads (8 groups of 128). Each group sums 16
// of the 128 L2-hot intermediate rows, smem-combine, then epilogue.
__global__ __launch_bounds__(1024)
void reduce2_kernel(float* __restrict__ out)
{
    __shared__ float smC[8][NWAVE];
    __shared__ float smS[8][NWAVE];
    __shared__ float smM[NWAVE];

    const int w = threadIdx.x & (NWAVE - 1);
    const int g = threadIdx.x >> 7;

    float c = 0.0f, s = 0.0f;
    #pragma unroll
    for (int r = g; r < RB; r += 8) {            // 16 coalesced loads each
        c += g2C[r * NWAVE + w];
        s += g2S[r * NWAVE + w];
    }
    smC[g][w] = c;
    smS[g][w] = s;
    __syncthreads();

    if (g == 0) {
        float fc = 0.0f, fs = 0.0f;
        #pragma unroll
        for (int k = 0; k < 8; k++) { fc += smC[k][w]; fs += smS[k][w]; }

        const float C = fc * (1.0f / (float)NPOINTS);
        const float S = fs * (1.0f / (float)NPOINTS);

        float m = -3.402823466e38f;
        #pragma unroll
        for (int i = 0; i < NOFFSETS; i++) {
            const float o = (float)i * (TWO_PI / (float)(NOFFSETS - 1));
            const float v = C * cosf(o) - S * sinf(o);
            m = fmaxf(m, v);
        }
        smM[w] = m;
    }
    __syncthreads();

    #pragma unroll
    for (int stride = NWAVE / 2; stride > 0; stride >>= 1) {
        if (threadIdx.x < stride) smM[threadIdx.x] += smM[threadIdx.x + stride];
        __syncthreads();
    }
    if (threadIdx.x == 0) out[0] = -smM[0];
}

extern "C" void kernel_launch(void* const* d_in, const int* in_sizes, int n_in,
                              void* d_out, int out_size)
{
    const float2* xy         = (const float2*)d_in[0];  // [500000, 2]
    const float*  tid        = (const float*) d_in[1];  // [500000, 128]
    const float*  center     = (const float*) d_in[2];  // [2]
    const float*  wavelength = (const float*) d_in[3];  // [128]
    float* out = (float*)d_out;

    accum_kernel<<<NBLK, TPB>>>(xy, tid, center, wavelength);
    reduce1_kernel<<<RB, 256>>>();
    reduce2_kernel<<<1, 1024>>>(out);
}